// round 7
// baseline (speedup 1.0000x reference)
#include <cuda_runtime.h>
#include <cuda_fp16.h>
#include <cstdint>

// ---------------- problem constants ----------------
#define NTOK  197
#define BTOT  128          // B*T
#define OC3   2304         // 3*C
#define NCOLS 25216        // BTOT*NTOK
#define OUTBT 453888       // OC3*NTOK

// ---------------- device scratch (static globals: allowed) ----------------
__device__ float  g_s[BTOT * OC3];              // routing scales, 1.18 MB
__device__ __half g_wth[OC3 * 768];             // fp16(W), 3.5 MB
__device__ __half g_xsh[3][NCOLS * 768];        // fp16(x*s) per group, 116 MB

// ---------------- helpers ----------------
__device__ __forceinline__ uint32_t smem_u32(const void* p) {
    uint32_t a;
    asm("{ .reg .u64 t; cvta.to.shared.u64 t, %1; cvt.u32.u64 %0, t; }" : "=r"(a) : "l"(p));
    return a;
}
__device__ __forceinline__ void cp_async16(uint32_t dst, const void* src) {
    asm volatile("cp.async.cg.shared.global [%0], [%1], 16;" :: "r"(dst), "l"(src) : "memory");
}
#define CP_COMMIT() asm volatile("cp.async.commit_group;" ::: "memory")
#define CP_WAIT2()  asm volatile("cp.async.wait_group 2;" ::: "memory")
#define CP_WAIT1()  asm volatile("cp.async.wait_group 1;" ::: "memory")
#define CP_WAIT0()  asm volatile("cp.async.wait_group 0;" ::: "memory")

#define LDSM_X4(r0, r1, r2, r3, addr) \
    asm volatile("ldmatrix.sync.aligned.m8n8.x4.shared.b16 {%0,%1,%2,%3}, [%4];" \
        : "=r"(r0), "=r"(r1), "=r"(r2), "=r"(r3) : "r"(addr))

#define SWZ(off) ((off) ^ (((off) >> 3) & 0x70))

// ---------------------------------------------------------------------------
// Routing: r[b,oc,t] = conv1d_k3(cls)[oc,t] + ab[oc] + 1 -> g_s[(b*8+t)*2304+oc]
// ---------------------------------------------------------------------------
__global__ __launch_bounds__(256) void routing_kernel(
    const float* __restrict__ x, const float* __restrict__ aw,
    const float* __restrict__ ab)
{
    __shared__ float cls[10][772];   // rows 1..8 = cls(t), 0/9 zero pad
    const int b   = blockIdx.x;
    const int oc  = blockIdx.y * 256 + threadIdx.x;
    const int tid = threadIdx.x;

    #pragma unroll
    for (int tp = 0; tp < 8; tp++)
        for (int ic = tid; ic < 768; ic += 256)
            cls[tp + 1][ic] = x[(size_t)((b * 8 + tp) * 197) * 768 + ic];
    for (int ic = tid; ic < 772; ic += 256) { cls[0][ic] = 0.f; cls[9][ic] = 0.f; }
    __syncthreads();

    const float* wr = aw + (size_t)oc * 2304;   // aw[oc][ic][k]
    float acc[8];
    #pragma unroll
    for (int t = 0; t < 8; t++) acc[t] = 0.f;

    for (int ic = 0; ic < 768; ic += 4) {
        float4 w0 = *(const float4*)(wr + ic * 3);
        float4 w1 = *(const float4*)(wr + ic * 3 + 4);
        float4 w2 = *(const float4*)(wr + ic * 3 + 8);
        float cv[10][4];
        #pragma unroll
        for (int j = 0; j < 10; j++) {
            cv[j][0] = cls[j][ic];     cv[j][1] = cls[j][ic + 1];
            cv[j][2] = cls[j][ic + 2]; cv[j][3] = cls[j][ic + 3];
        }
        #pragma unroll
        for (int t = 0; t < 8; t++) {
            acc[t] += cv[t][0] * w0.x + cv[t+1][0] * w0.y + cv[t+2][0] * w0.z;
            acc[t] += cv[t][1] * w0.w + cv[t+1][1] * w1.x + cv[t+2][1] * w1.y;
            acc[t] += cv[t][2] * w1.z + cv[t+1][2] * w1.w + cv[t+2][2] * w2.x;
            acc[t] += cv[t][3] * w2.y + cv[t+1][3] * w2.z + cv[t+2][3] * w2.w;
        }
    }
    float abv = ab[oc] + 1.0f;
    #pragma unroll
    for (int t = 0; t < 8; t++)
        g_s[(b * 8 + t) * 2304 + oc] = acc[t] + abv;
}

// ---------------------------------------------------------------------------
// Prep: W -> fp16(RN) ;  x,s -> fp16(x*s) per group
// ---------------------------------------------------------------------------
__global__ __launch_bounds__(256) void prep_w(const float* __restrict__ w)
{
    int i = (blockIdx.x * 256 + threadIdx.x) * 4;
    float4 v = *(const float4*)(w + i);
    __half2 h0 = __floats2half2_rn(v.x, v.y);
    __half2 h1 = __floats2half2_rn(v.z, v.w);
    uint2 o = { *(uint32_t*)&h0, *(uint32_t*)&h1 };
    *(uint2*)(&g_wth[i]) = o;
}

__global__ __launch_bounds__(192) void prep_xs(const float* __restrict__ x)
{
    const int col = blockIdx.x;
    const int k   = threadIdx.x * 4;
    const int bt  = col / 197;
    float4 xv = *(const float4*)(x + (size_t)col * 768 + k);
    #pragma unroll
    for (int g = 0; g < 3; g++) {
        float4 sv = *(const float4*)(g_s + bt * 2304 + g * 768 + k);
        __half2 h0 = __floats2half2_rn(xv.x * sv.x, xv.y * sv.y);
        __half2 h1 = __floats2half2_rn(xv.z * sv.z, xv.w * sv.w);
        uint2 o = { *(uint32_t*)&h0, *(uint32_t*)&h1 };
        *(uint2*)(&g_xsh[g][(size_t)col * 768 + k]) = o;
    }
}

// ---------------------------------------------------------------------------
// Main GEMM (mma.sync fp16 m16n8k16): per g, out[o,cj] = sum_k Wh[o,k]*Xh[cj,k]
// CTA tile 256x128, BK=64 halfs, 12 chunks, 4-stage cp.async, tail-exact waits.
// 8 warps = 4(m) x 2(n): warp tile 64x64. 1 CTA/SM. grid=(9,197), block 256.
// ---------------------------------------------------------------------------
#define STAGES      4
#define A_BYTES     32768            // 256 rows x 128B
#define B_BYTES     16384            // 128 rows x 128B
#define STAGE_BYTES (A_BYTES + B_BYTES)
#define SMEM_MAIN   (STAGES * STAGE_BYTES)   // 196608
#define NCHUNK      12

__global__ __launch_bounds__(256, 1)
void tal_main_kernel(const float* __restrict__ bias, float* __restrict__ out)
{
    extern __shared__ char smem[];
    const uint32_t sb = smem_u32(smem);

    const int bx   = blockIdx.x;          // 0..8
    const int g    = bx / 3, mt = bx % 3;  // mt: 256-row M tile
    const int col0 = blockIdx.y * 128;
    const int tid  = threadIdx.x;
    const int lane = tid & 31, warp = tid >> 5;
    const int wm = warp & 3, wn = warp >> 2;      // 4x2 warp grid, 64x64 tiles
    const int lr = lane >> 2, lc = lane & 3;

    // ---- cp.async addressing: one base each; constant strides ----
    const int r0 = tid >> 3, q8 = (tid & 7) * 8;        // 8 halfs = 16B granule
    const uint32_t dst0 = SWZ((uint32_t)(r0 * 128 + q8 * 2));
    const __half* aptr = g_wth + (size_t)(g * 768 + mt * 256 + r0) * 768 + q8;
    const __half* bptr = g_xsh[g] + (size_t)(col0 + r0) * 768 + q8;

    // ---- ldmatrix base offsets (ks=0); per-ks addr = base ^ (ks*32) ----
    const int alrow = lane & 15, aqhi = lane >> 4;
    const int brow = (lane & 7) | ((lane & 16) >> 1), bq = (lane >> 3) & 1;
    uint32_t aoff[4], boff[4];
    #pragma unroll
    for (int mi = 0; mi < 4; mi++)
        aoff[mi] = SWZ((uint32_t)((wm * 64 + mi * 16 + alrow) * 128 + aqhi * 16));
    #pragma unroll
    for (int nj = 0; nj < 4; nj++)
        boff[nj] = SWZ((uint32_t)((wn * 64 + nj * 16 + brow) * 128 + bq * 16));

    float acc[4][8][4];
    #pragma unroll
    for (int mi = 0; mi < 4; mi++)
        #pragma unroll
        for (int ni = 0; ni < 8; ni++)
            #pragma unroll
            for (int e = 0; e < 4; e++) acc[mi][ni][e] = 0.f;

    auto COPY = [&](int st, int c) {
        const uint32_t sA = sb + st * STAGE_BYTES;
        const uint32_t sB = sA + A_BYTES;
        const __half* ap = aptr + c * 64;
        const __half* bp = bptr + c * 64;
        #pragma unroll
        for (int i = 0; i < 8; i++)            // A: 256 rows, 32 rows/pass
            cp_async16(sA + dst0 + i * 4096, ap + i * 24576);
        #pragma unroll
        for (int i = 0; i < 4; i++)            // B: 128 rows, 32 rows/pass
            cp_async16(sB + dst0 + i * 4096, bp + i * 24576);
    };

    COPY(0, 0); CP_COMMIT();
    COPY(1, 1); CP_COMMIT();
    COPY(2, 2); CP_COMMIT();

    #pragma unroll 1
    for (int c = 0; c < NCHUNK; c++) {
        if (c <= NCHUNK - 3)      { CP_WAIT2(); }
        else if (c == NCHUNK - 2) { CP_WAIT1(); }
        else                      { CP_WAIT0(); }
        __syncthreads();
        if (c + 3 < NCHUNK) { COPY((c + 3) & 3, c + 3); CP_COMMIT(); }

        const uint32_t sA = sb + (c & 3) * STAGE_BYTES;
        const uint32_t sB = sA + A_BYTES;

        #pragma unroll
        for (int ks = 0; ks < 4; ks++) {           // k16 steps within 64-half chunk
            const uint32_t kx = (uint32_t)(ks * 32);
            uint32_t a[4][4], b[4][4];
            #pragma unroll
            for (int mi = 0; mi < 4; mi++)
                LDSM_X4(a[mi][0], a[mi][1], a[mi][2], a[mi][3], sA + (aoff[mi] ^ kx));
            #pragma unroll
            for (int nj = 0; nj < 4; nj++)
                LDSM_X4(b[nj][0], b[nj][1], b[nj][2], b[nj][3], sB + (boff[nj] ^ kx));
            #pragma unroll
            for (int mi = 0; mi < 4; mi++)
                #pragma unroll
                for (int ni = 0; ni < 8; ni++) {
                    const uint32_t b0 = b[ni >> 1][(ni & 1) * 2];
                    const uint32_t b1 = b[ni >> 1][(ni & 1) * 2 + 1];
                    asm volatile(
                        "mma.sync.aligned.m16n8k16.row.col.f32.f16.f16.f32 "
                        "{%0,%1,%2,%3},{%4,%5,%6,%7},{%8,%9},{%0,%1,%2,%3};\n"
                        : "+f"(acc[mi][ni][0]), "+f"(acc[mi][ni][1]),
                          "+f"(acc[mi][ni][2]), "+f"(acc[mi][ni][3])
                        : "r"(a[mi][0]), "r"(a[mi][1]), "r"(a[mi][2]), "r"(a[mi][3]),
                          "r"(b0), "r"(b1));
                }
        }
    }

    // ---- epilogue: out[bt, oc, n] = acc + bias[oc]*s[bt,oc] ----
    const int bt_base = col0 / 197;
    const int col197  = (bt_base + 1) * 197;
    int bt1 = bt_base + 1; if (bt1 > 127) bt1 = 127;

    float bvsv[4][2][2];
    #pragma unroll
    for (int mi = 0; mi < 4; mi++)
        #pragma unroll
        for (int h = 0; h < 2; h++) {
            int oc = g * 768 + mt * 256 + wm * 64 + mi * 16 + lr + h * 8;
            float bv = bias[oc];
            bvsv[mi][h][0] = bv * g_s[bt_base * 2304 + oc];
            bvsv[mi][h][1] = bv * g_s[bt1 * 2304 + oc];
        }

    #pragma unroll
    for (int mi = 0; mi < 4; mi++)
        #pragma unroll
        for (int ni = 0; ni < 8; ni++)
            #pragma unroll
            for (int e = 0; e < 4; e++) {
                const int h   = e >> 1;
                const int oc  = g * 768 + mt * 256 + wm * 64 + mi * 16 + lr + h * 8;
                const int col = col0 + wn * 64 + ni * 8 + lc * 2 + (e & 1);
                const int bs  = (col >= col197) ? 1 : 0;
                const float add = bs ? bvsv[mi][h][1] : bvsv[mi][h][0];
                // idx = bt*OUTBT + oc*197 + (col - bt*197) = col + oc*197 + bt*453691
                const size_t idx = (size_t)col + (size_t)oc * 197
                                 + (size_t)(bt_base + bs) * 453691;
                out[idx] = acc[mi][ni][e] + add;
            }
}

extern "C" void kernel_launch(void* const* d_in, const int* in_sizes, int n_in,
                              void* d_out, int out_size)
{
    const float* x    = (const float*)d_in[0];
    const float* aw   = (const float*)d_in[1];
    const float* ab   = (const float*)d_in[2];
    const float* w    = (const float*)d_in[3];
    const float* bias = (const float*)d_in[4];
    float* out = (float*)d_out;

    cudaFuncSetAttribute(tal_main_kernel,
                         cudaFuncAttributeMaxDynamicSharedMemorySize, SMEM_MAIN);

    routing_kernel<<<dim3(16, 9), 256>>>(x, aw, ab);
    prep_w<<<OC3 * 768 / 1024, 256>>>(w);
    prep_xs<<<NCOLS, 192>>>(x);
    tal_main_kernel<<<dim3(9, 197), 256, SMEM_MAIN>>>(bias, out);
}

// round 8
// speedup vs baseline: 1.4901x; 1.4901x over previous
#include <cuda_runtime.h>
#include <cuda_fp16.h>
#include <cstdint>

// ---------------- problem constants ----------------
#define NTOK  197
#define BTOT  128          // B*T
#define OC3   2304         // 3*C
#define NCOLS 25216        // BTOT*NTOK
#define OUTBT 453888       // OC3*NTOK

// ---------------- device scratch (static globals: allowed) ----------------
__device__ float  g_s[BTOT * OC3];              // routing scales, 1.18 MB
__device__ __half g_wth[OC3 * 768];             // fp16(W), 3.5 MB
__device__ __half g_xsh[3][NCOLS * 768];        // fp16(x*s) per group, 116 MB

// ---------------- helpers ----------------
__device__ __forceinline__ uint32_t smem_u32(const void* p) {
    uint32_t a;
    asm("{ .reg .u64 t; cvta.to.shared.u64 t, %1; cvt.u32.u64 %0, t; }" : "=r"(a) : "l"(p));
    return a;
}
__device__ __forceinline__ void cp_async16(uint32_t dst, const void* src) {
    asm volatile("cp.async.cg.shared.global [%0], [%1], 16;" :: "r"(dst), "l"(src) : "memory");
}
#define CP_COMMIT() asm volatile("cp.async.commit_group;" ::: "memory")
#define CP_WAIT2()  asm volatile("cp.async.wait_group 2;" ::: "memory")
#define CP_WAIT1()  asm volatile("cp.async.wait_group 1;" ::: "memory")
#define CP_WAIT0()  asm volatile("cp.async.wait_group 0;" ::: "memory")

#define LDSM_X4(r0, r1, r2, r3, addr) \
    asm volatile("ldmatrix.sync.aligned.m8n8.x4.shared.b16 {%0,%1,%2,%3}, [%4];" \
        : "=r"(r0), "=r"(r1), "=r"(r2), "=r"(r3) : "r"(addr))

#define SWZ(off) ((off) ^ (((off) >> 3) & 0x70))

// ---------------------------------------------------------------------------
// Routing: r[b,oc,t] = conv1d_k3(cls)[oc,t] + ab[oc] + 1 -> g_s[(b*8+t)*2304+oc]
// ---------------------------------------------------------------------------
__global__ __launch_bounds__(256) void routing_kernel(
    const float* __restrict__ x, const float* __restrict__ aw,
    const float* __restrict__ ab)
{
    __shared__ float cls[10][772];   // rows 1..8 = cls(t), 0/9 zero pad
    const int b   = blockIdx.x;
    const int oc  = blockIdx.y * 256 + threadIdx.x;
    const int tid = threadIdx.x;

    #pragma unroll
    for (int tp = 0; tp < 8; tp++)
        for (int ic = tid; ic < 768; ic += 256)
            cls[tp + 1][ic] = x[(size_t)((b * 8 + tp) * 197) * 768 + ic];
    for (int ic = tid; ic < 772; ic += 256) { cls[0][ic] = 0.f; cls[9][ic] = 0.f; }
    __syncthreads();

    const float* wr = aw + (size_t)oc * 2304;   // aw[oc][ic][k]
    float acc[8];
    #pragma unroll
    for (int t = 0; t < 8; t++) acc[t] = 0.f;

    for (int ic = 0; ic < 768; ic += 4) {
        float4 w0 = *(const float4*)(wr + ic * 3);
        float4 w1 = *(const float4*)(wr + ic * 3 + 4);
        float4 w2 = *(const float4*)(wr + ic * 3 + 8);
        float cv[10][4];
        #pragma unroll
        for (int j = 0; j < 10; j++) {
            cv[j][0] = cls[j][ic];     cv[j][1] = cls[j][ic + 1];
            cv[j][2] = cls[j][ic + 2]; cv[j][3] = cls[j][ic + 3];
        }
        #pragma unroll
        for (int t = 0; t < 8; t++) {
            acc[t] += cv[t][0] * w0.x + cv[t+1][0] * w0.y + cv[t+2][0] * w0.z;
            acc[t] += cv[t][1] * w0.w + cv[t+1][1] * w1.x + cv[t+2][1] * w1.y;
            acc[t] += cv[t][2] * w1.z + cv[t+1][2] * w1.w + cv[t+2][2] * w2.x;
            acc[t] += cv[t][3] * w2.y + cv[t+1][3] * w2.z + cv[t+2][3] * w2.w;
        }
    }
    float abv = ab[oc] + 1.0f;
    #pragma unroll
    for (int t = 0; t < 8; t++)
        g_s[(b * 8 + t) * 2304 + oc] = acc[t] + abv;
}

// ---------------------------------------------------------------------------
// Prep: W -> fp16(RN) ;  x,s -> fp16(x*s) per group
// ---------------------------------------------------------------------------
__global__ __launch_bounds__(256) void prep_w(const float* __restrict__ w)
{
    int i = (blockIdx.x * 256 + threadIdx.x) * 4;
    float4 v = *(const float4*)(w + i);
    __half2 h0 = __floats2half2_rn(v.x, v.y);
    __half2 h1 = __floats2half2_rn(v.z, v.w);
    uint2 o = { *(uint32_t*)&h0, *(uint32_t*)&h1 };
    *(uint2*)(&g_wth[i]) = o;
}

__global__ __launch_bounds__(192) void prep_xs(const float* __restrict__ x)
{
    const int col = blockIdx.x;
    const int k   = threadIdx.x * 4;
    const int bt  = col / 197;
    float4 xv = *(const float4*)(x + (size_t)col * 768 + k);
    #pragma unroll
    for (int g = 0; g < 3; g++) {
        float4 sv = *(const float4*)(g_s + bt * 2304 + g * 768 + k);
        __half2 h0 = __floats2half2_rn(xv.x * sv.x, xv.y * sv.y);
        __half2 h1 = __floats2half2_rn(xv.z * sv.z, xv.w * sv.w);
        uint2 o = { *(uint32_t*)&h0, *(uint32_t*)&h1 };
        *(uint2*)(&g_xsh[g][(size_t)col * 768 + k]) = o;
    }
}

// ---------------------------------------------------------------------------
// Main GEMM (mma.sync fp16 m16n8k16): per g, out[o,cj] = sum_k Wh[o,k]*Xh[cj,k]
// CTA tile 256x128, BK=64 halfs, 12 chunks, 4-stage cp.async, tail-exact waits.
// 8 warps = 4(m) x 2(n): warp tile 64x64. 1 CTA/SM. grid=(9,197), block 256.
// ---------------------------------------------------------------------------
#define STAGES      4
#define A_BYTES     32768            // 256 rows x 128B
#define B_BYTES     16384            // 128 rows x 128B
#define STAGE_BYTES (A_BYTES + B_BYTES)
#define SMEM_MAIN   (STAGES * STAGE_BYTES)   // 196608
#define NCHUNK      12

__global__ __launch_bounds__(256, 1)
void tal_main_kernel(const float* __restrict__ bias, float* __restrict__ out)
{
    extern __shared__ char smem[];
    const uint32_t sb = smem_u32(smem);

    const int bx   = blockIdx.x;          // 0..8
    const int g    = bx / 3, mt = bx % 3;  // mt: 256-row M tile
    const int col0 = blockIdx.y * 128;
    const int tid  = threadIdx.x;
    const int lane = tid & 31, warp = tid >> 5;
    const int wm = warp & 3, wn = warp >> 2;      // 4x2 warp grid, 64x64 tiles
    const int lr = lane >> 2, lc = lane & 3;

    // ---- cp.async addressing: one base each; constant strides ----
    const int r0 = tid >> 3, q8 = (tid & 7) * 8;        // 8 halfs = 16B granule
    const uint32_t dst0 = SWZ((uint32_t)(r0 * 128 + q8 * 2));
    const __half* aptr = g_wth + (size_t)(g * 768 + mt * 256 + r0) * 768 + q8;
    const __half* bptr = g_xsh[g] + (size_t)(col0 + r0) * 768 + q8;

    // ---- ldmatrix base offsets (ks=0); per-ks addr = base ^ (ks*32) ----
    const int alrow = lane & 15, aqhi = lane >> 4;
    const int brow = (lane & 7) | ((lane & 16) >> 1), bq = (lane >> 3) & 1;
    uint32_t aoff[4], boff[4];
    #pragma unroll
    for (int mi = 0; mi < 4; mi++)
        aoff[mi] = SWZ((uint32_t)((wm * 64 + mi * 16 + alrow) * 128 + aqhi * 16));
    #pragma unroll
    for (int nj = 0; nj < 4; nj++)
        boff[nj] = SWZ((uint32_t)((wn * 64 + nj * 16 + brow) * 128 + bq * 16));

    float acc[4][8][4];
    #pragma unroll
    for (int mi = 0; mi < 4; mi++)
        #pragma unroll
        for (int ni = 0; ni < 8; ni++)
            #pragma unroll
            for (int e = 0; e < 4; e++) acc[mi][ni][e] = 0.f;

    auto COPY = [&](int st, int c) {
        const uint32_t sA = sb + st * STAGE_BYTES;
        const uint32_t sB = sA + A_BYTES;
        const __half* ap = aptr + c * 64;
        const __half* bp = bptr + c * 64;
        #pragma unroll
        for (int i = 0; i < 8; i++)            // A: 256 rows, 32 rows/pass
            cp_async16(sA + dst0 + i * 4096, ap + i * 24576);
        #pragma unroll
        for (int i = 0; i < 4; i++)            // B: 128 rows, 32 rows/pass
            cp_async16(sB + dst0 + i * 4096, bp + i * 24576);
    };

    COPY(0, 0); CP_COMMIT();
    COPY(1, 1); CP_COMMIT();
    COPY(2, 2); CP_COMMIT();

    #pragma unroll 1
    for (int c = 0; c < NCHUNK; c++) {
        if (c <= NCHUNK - 3)      { CP_WAIT2(); }
        else if (c == NCHUNK - 2) { CP_WAIT1(); }
        else                      { CP_WAIT0(); }
        __syncthreads();
        if (c + 3 < NCHUNK) { COPY((c + 3) & 3, c + 3); CP_COMMIT(); }

        const uint32_t sA = sb + (c & 3) * STAGE_BYTES;
        const uint32_t sB = sA + A_BYTES;

        #pragma unroll
        for (int ks = 0; ks < 4; ks++) {           // k16 steps within 64-half chunk
            const uint32_t kx = (uint32_t)(ks * 32);
            uint32_t a[4][4], b[4][4];
            #pragma unroll
            for (int mi = 0; mi < 4; mi++)
                LDSM_X4(a[mi][0], a[mi][1], a[mi][2], a[mi][3], sA + (aoff[mi] ^ kx));
            #pragma unroll
            for (int nj = 0; nj < 4; nj++)
                LDSM_X4(b[nj][0], b[nj][1], b[nj][2], b[nj][3], sB + (boff[nj] ^ kx));
            #pragma unroll
            for (int mi = 0; mi < 4; mi++)
                #pragma unroll
                for (int ni = 0; ni < 8; ni++) {
                    const uint32_t b0 = b[ni >> 1][(ni & 1) * 2];
                    const uint32_t b1 = b[ni >> 1][(ni & 1) * 2 + 1];
                    asm volatile(
                        "mma.sync.aligned.m16n8k16.row.col.f32.f16.f16.f32 "
                        "{%0,%1,%2,%3},{%4,%5,%6,%7},{%8,%9},{%0,%1,%2,%3};\n"
                        : "+f"(acc[mi][ni][0]), "+f"(acc[mi][ni][1]),
                          "+f"(acc[mi][ni][2]), "+f"(acc[mi][ni][3])
                        : "r"(a[mi][0]), "r"(a[mi][1]), "r"(a[mi][2]), "r"(a[mi][3]),
                          "r"(b0), "r"(b1));
                }
        }
    }

    // ---- epilogue: out[bt, oc, n] = acc + bias[oc]*s[bt,oc] ----
    const int bt_base = col0 / 197;
    const int col197  = (bt_base + 1) * 197;
    int bt1 = bt_base + 1; if (bt1 > 127) bt1 = 127;

    float bvsv[4][2][2];
    #pragma unroll
    for (int mi = 0; mi < 4; mi++)
        #pragma unroll
        for (int h = 0; h < 2; h++) {
            int oc = g * 768 + mt * 256 + wm * 64 + mi * 16 + lr + h * 8;
            float bv = bias[oc];
            bvsv[mi][h][0] = bv * g_s[bt_base * 2304 + oc];
            bvsv[mi][h][1] = bv * g_s[bt1 * 2304 + oc];
        }

    #pragma unroll
    for (int mi = 0; mi < 4; mi++)
        #pragma unroll
        for (int ni = 0; ni < 8; ni++)
            #pragma unroll
            for (int e = 0; e < 4; e++) {
                const int h   = e >> 1;
                const int oc  = g * 768 + mt * 256 + wm * 64 + mi * 16 + lr + h * 8;
                const int col = col0 + wn * 64 + ni * 8 + lc * 2 + (e & 1);
                const int bs  = (col >= col197) ? 1 : 0;
                const float add = bs ? bvsv[mi][h][1] : bvsv[mi][h][0];
                // idx = bt*OUTBT + oc*197 + (col - bt*197) = col + oc*197 + bt*453691
                const size_t idx = (size_t)col + (size_t)oc * 197
                                 + (size_t)(bt_base + bs) * 453691;
                out[idx] = acc[mi][ni][e] + add;
            }
}

extern "C" void kernel_launch(void* const* d_in, const int* in_sizes, int n_in,
                              void* d_out, int out_size)
{
    const float* x    = (const float*)d_in[0];
    const float* aw   = (const float*)d_in[1];
    const float* ab   = (const float*)d_in[2];
    const float* w    = (const float*)d_in[3];
    const float* bias = (const float*)d_in[4];
    float* out = (float*)d_out;

    cudaFuncSetAttribute(tal_main_kernel,
                         cudaFuncAttributeMaxDynamicSharedMemorySize, SMEM_MAIN);

    routing_kernel<<<dim3(16, 9), 256>>>(x, aw, ab);
    prep_w<<<OC3 * 768 / 1024, 256>>>(w);
    prep_xs<<<NCOLS, 192>>>(x);
    tal_main_kernel<<<dim3(9, 197), 256, SMEM_MAIN>>>(bias, out);
}